// round 5
// baseline (speedup 1.0000x reference)
#include <cuda_runtime.h>
#include <cuda_bf16.h>

// Problem: ToRGBLayer  (B=16, CIN=128, COUT=3, WDIM=512, H=W=256)
// out[b,o,h,w] = sum_i x[b,i,h,w] * style[b,i] * weight[o,i] + bias[o]
// style[b,i]   = dot(w[b,:], affine_w[i,:]) + affine_b[i]
//
// R5: R4 (best, 84.5us) + programmatic dependent launch. torgb is launched
// with the PDL attribute so its launch/dispatch/preamble overlaps the style
// kernel; a cudaGridDependencySynchronize() guards the g_coeff read. style
// fires cudaTriggerProgrammaticLaunchCompletion() right after its store.
// Streaming loop itself is UNCHANGED (32 regs, 8 CTA/SM, __ldcs/__stcg).

#define B_    16
#define CIN_  128
#define COUT_ 3
#define WDIM_ 512
#define HW_   65536            // 256*256
#define HW4_  16384            // HW/4 float4 positions

// Scratch: coeff[b][i] = {style*w0, style*w1, style*w2, 0}
__device__ float4 g_coeff[B_ * CIN_];

// ---------------------------------------------------------------------------
// Kernel 1: coeff. One warp per (b,i). 2048 warps = 256 blocks x 256 threads.
// ---------------------------------------------------------------------------
__global__ void __launch_bounds__(256) style_kernel(
    const float4* __restrict__ w,         // [B, WDIM/4]
    const float*  __restrict__ weight,    // [COUT, CIN] (1x1 conv squeezed)
    const float4* __restrict__ affine_w,  // [CIN, WDIM/4]
    const float*  __restrict__ affine_b)  // [CIN]
{
    const int lane = threadIdx.x & 31;
    const int gw   = (blockIdx.x << 3) + (threadIdx.x >> 5);  // global warp id
    const int b    = gw >> 7;          // / CIN_
    const int i    = gw & (CIN_ - 1);

    const float4* wb = w + b * (WDIM_ / 4);
    const float4* aw = affine_w + i * (WDIM_ / 4);

    float acc = 0.f;
    #pragma unroll
    for (int k = 0; k < 4; k++) {
        float4 a = wb[lane + 32 * k];
        float4 c = aw[lane + 32 * k];
        acc += a.x * c.x + a.y * c.y + a.z * c.z + a.w * c.w;
    }
    #pragma unroll
    for (int off = 16; off > 0; off >>= 1)
        acc += __shfl_down_sync(0xffffffffu, acc, off);

    if (lane == 0) {
        float style = acc + affine_b[i];
        float4 c;
        c.x = style * weight[0 * CIN_ + i];
        c.y = style * weight[1 * CIN_ + i];
        c.z = style * weight[2 * CIN_ + i];
        c.w = 0.f;
        g_coeff[b * CIN_ + i] = c;
    }

    // Release the PDL dependency as soon as this block's work is done
    // (membar implied by the trigger's release semantics).
    cudaTriggerProgrammaticLaunchCompletion();
}

// ---------------------------------------------------------------------------
// Kernel 2: streaming pass. grid = (HW4_/256, B), 256 threads, 8 CTA/SM.
// Each thread owns one float4 hw-position, loops 128 channels (unroll 4),
// evict-first loads on x, evict-normal L2 stores on out.
// ---------------------------------------------------------------------------
__global__ void __launch_bounds__(256, 8) torgb_kernel(
    const float4* __restrict__ x,     // [B, CIN, HW4_] as float4
    const float*  __restrict__ bias,  // [COUT]
    float4*       __restrict__ out)   // [B, COUT, HW4_] as float4
{
    __shared__ float4 sc[CIN_];

    const int tid = threadIdx.x;
    const int b   = blockIdx.y;

    // Address setup can proceed before the producer finishes.
    const size_t idx4 = (size_t)blockIdx.x * 256 + tid;
    const float4* xb  = x + ((size_t)b * CIN_) * HW4_ + idx4;

    // Wait for style_kernel's g_coeff writes (PDL edge), then stage coeffs.
    cudaGridDependencySynchronize();

    if (tid < CIN_) sc[tid] = g_coeff[b * CIN_ + tid];
    __syncthreads();

    float4 a0 = make_float4(0.f, 0.f, 0.f, 0.f);
    float4 a1 = a0, a2 = a0;

    #pragma unroll 4
    for (int i = 0; i < CIN_; i++) {
        float4 v = __ldcs(&xb[(size_t)i * HW4_]);
        float4 c = sc[i];
        a0.x += v.x * c.x; a0.y += v.y * c.x; a0.z += v.z * c.x; a0.w += v.w * c.x;
        a1.x += v.x * c.y; a1.y += v.y * c.y; a1.z += v.z * c.y; a1.w += v.w * c.y;
        a2.x += v.x * c.z; a2.y += v.y * c.z; a2.z += v.z * c.z; a2.w += v.w * c.z;
    }

    const float b0 = bias[0], b1 = bias[1], b2 = bias[2];
    a0.x += b0; a0.y += b0; a0.z += b0; a0.w += b0;
    a1.x += b1; a1.y += b1; a1.z += b1; a1.w += b1;
    a2.x += b2; a2.y += b2; a2.z += b2; a2.w += b2;

    float4* ob = out + ((size_t)b * COUT_) * HW4_ + idx4;
    __stcg(&ob[0 * HW4_], a0);
    __stcg(&ob[1 * HW4_], a1);
    __stcg(&ob[2 * HW4_], a2);
}

// ---------------------------------------------------------------------------
// Launch. Input order (metadata): x, w, weight, bias, affine_w, affine_b
// ---------------------------------------------------------------------------
extern "C" void kernel_launch(void* const* d_in, const int* in_sizes, int n_in,
                              void* d_out, int out_size)
{
    const float*  x        = (const float*)d_in[0];
    const float*  w        = (const float*)d_in[1];
    const float*  weight   = (const float*)d_in[2];
    const float*  bias     = (const float*)d_in[3];
    const float*  affine_w = (const float*)d_in[4];
    const float*  affine_b = (const float*)d_in[5];
    float* out = (float*)d_out;

    style_kernel<<<(B_ * CIN_) / 8, 256>>>((const float4*)w, weight,
                                           (const float4*)affine_w, affine_b);

    // Secondary kernel with programmatic dependent launch: overlaps its
    // launch/dispatch with style_kernel; g_coeff read is guarded in-kernel.
    cudaLaunchConfig_t cfg = {};
    cfg.gridDim  = dim3(HW4_ / 256, B_);
    cfg.blockDim = dim3(256);
    cfg.dynamicSmemBytes = 0;
    cfg.stream = 0;

    cudaLaunchAttribute attrs[1];
    attrs[0].id = cudaLaunchAttributeProgrammaticStreamSerialization;
    attrs[0].val.programmaticStreamSerializationAllowed = 1;
    cfg.attrs = attrs;
    cfg.numAttrs = 1;

    cudaLaunchKernelEx(&cfg, torgb_kernel, (const float4*)x, bias, (float4*)out);
}

// round 6
// speedup vs baseline: 1.0107x; 1.0107x over previous
#include <cuda_runtime.h>
#include <cuda_bf16.h>

// Problem: ToRGBLayer  (B=16, CIN=128, COUT=3, WDIM=512, H=W=256)
// out[b,o,h,w] = sum_i x[b,i,h,w] * style[b,i] * weight[o,i] + bias[o]
// style[b,i]   = dot(w[b,:], affine_w[i,:]) + affine_b[i]
//
// R5: R4 (best, 84.5us) + programmatic dependent launch. torgb is launched
// with the PDL attribute so its launch/dispatch/preamble overlaps the style
// kernel; a cudaGridDependencySynchronize() guards the g_coeff read. style
// fires cudaTriggerProgrammaticLaunchCompletion() right after its store.
// Streaming loop itself is UNCHANGED (32 regs, 8 CTA/SM, __ldcs/__stcg).

#define B_    16
#define CIN_  128
#define COUT_ 3
#define WDIM_ 512
#define HW_   65536            // 256*256
#define HW4_  16384            // HW/4 float4 positions

// Scratch: coeff[b][i] = {style*w0, style*w1, style*w2, 0}
__device__ float4 g_coeff[B_ * CIN_];

// ---------------------------------------------------------------------------
// Kernel 1: coeff. One warp per (b,i). 2048 warps = 256 blocks x 256 threads.
// ---------------------------------------------------------------------------
__global__ void __launch_bounds__(256) style_kernel(
    const float4* __restrict__ w,         // [B, WDIM/4]
    const float*  __restrict__ weight,    // [COUT, CIN] (1x1 conv squeezed)
    const float4* __restrict__ affine_w,  // [CIN, WDIM/4]
    const float*  __restrict__ affine_b)  // [CIN]
{
    const int lane = threadIdx.x & 31;
    const int gw   = (blockIdx.x << 3) + (threadIdx.x >> 5);  // global warp id
    const int b    = gw >> 7;          // / CIN_
    const int i    = gw & (CIN_ - 1);

    const float4* wb = w + b * (WDIM_ / 4);
    const float4* aw = affine_w + i * (WDIM_ / 4);

    float acc = 0.f;
    #pragma unroll
    for (int k = 0; k < 4; k++) {
        float4 a = wb[lane + 32 * k];
        float4 c = aw[lane + 32 * k];
        acc += a.x * c.x + a.y * c.y + a.z * c.z + a.w * c.w;
    }
    #pragma unroll
    for (int off = 16; off > 0; off >>= 1)
        acc += __shfl_down_sync(0xffffffffu, acc, off);

    if (lane == 0) {
        float style = acc + affine_b[i];
        float4 c;
        c.x = style * weight[0 * CIN_ + i];
        c.y = style * weight[1 * CIN_ + i];
        c.z = style * weight[2 * CIN_ + i];
        c.w = 0.f;
        g_coeff[b * CIN_ + i] = c;
    }

    // Release the PDL dependency as soon as this block's work is done
    // (membar implied by the trigger's release semantics).
    cudaTriggerProgrammaticLaunchCompletion();
}

// ---------------------------------------------------------------------------
// Kernel 2: streaming pass. grid = (HW4_/256, B), 256 threads, 8 CTA/SM.
// Each thread owns one float4 hw-position, loops 128 channels (unroll 4),
// evict-first loads on x, evict-normal L2 stores on out.
// ---------------------------------------------------------------------------
__global__ void __launch_bounds__(256, 8) torgb_kernel(
    const float4* __restrict__ x,     // [B, CIN, HW4_] as float4
    const float*  __restrict__ bias,  // [COUT]
    float4*       __restrict__ out)   // [B, COUT, HW4_] as float4
{
    __shared__ float4 sc[CIN_];

    const int tid = threadIdx.x;
    const int b   = blockIdx.y;

    // Address setup can proceed before the producer finishes.
    const size_t idx4 = (size_t)blockIdx.x * 256 + tid;
    const float4* xb  = x + ((size_t)b * CIN_) * HW4_ + idx4;

    // Wait for style_kernel's g_coeff writes (PDL edge), then stage coeffs.
    cudaGridDependencySynchronize();

    if (tid < CIN_) sc[tid] = g_coeff[b * CIN_ + tid];
    __syncthreads();

    float4 a0 = make_float4(0.f, 0.f, 0.f, 0.f);
    float4 a1 = a0, a2 = a0;

    #pragma unroll 4
    for (int i = 0; i < CIN_; i++) {
        float4 v = __ldcs(&xb[(size_t)i * HW4_]);
        float4 c = sc[i];
        a0.x += v.x * c.x; a0.y += v.y * c.x; a0.z += v.z * c.x; a0.w += v.w * c.x;
        a1.x += v.x * c.y; a1.y += v.y * c.y; a1.z += v.z * c.y; a1.w += v.w * c.y;
        a2.x += v.x * c.z; a2.y += v.y * c.z; a2.z += v.z * c.z; a2.w += v.w * c.z;
    }

    const float b0 = bias[0], b1 = bias[1], b2 = bias[2];
    a0.x += b0; a0.y += b0; a0.z += b0; a0.w += b0;
    a1.x += b1; a1.y += b1; a1.z += b1; a1.w += b1;
    a2.x += b2; a2.y += b2; a2.z += b2; a2.w += b2;

    float4* ob = out + ((size_t)b * COUT_) * HW4_ + idx4;
    __stcg(&ob[0 * HW4_], a0);
    __stcg(&ob[1 * HW4_], a1);
    __stcg(&ob[2 * HW4_], a2);
}

// ---------------------------------------------------------------------------
// Launch. Input order (metadata): x, w, weight, bias, affine_w, affine_b
// ---------------------------------------------------------------------------
extern "C" void kernel_launch(void* const* d_in, const int* in_sizes, int n_in,
                              void* d_out, int out_size)
{
    const float*  x        = (const float*)d_in[0];
    const float*  w        = (const float*)d_in[1];
    const float*  weight   = (const float*)d_in[2];
    const float*  bias     = (const float*)d_in[3];
    const float*  affine_w = (const float*)d_in[4];
    const float*  affine_b = (const float*)d_in[5];
    float* out = (float*)d_out;

    style_kernel<<<(B_ * CIN_) / 8, 256>>>((const float4*)w, weight,
                                           (const float4*)affine_w, affine_b);

    // Secondary kernel with programmatic dependent launch: overlaps its
    // launch/dispatch with style_kernel; g_coeff read is guarded in-kernel.
    cudaLaunchConfig_t cfg = {};
    cfg.gridDim  = dim3(HW4_ / 256, B_);
    cfg.blockDim = dim3(256);
    cfg.dynamicSmemBytes = 0;
    cfg.stream = 0;

    cudaLaunchAttribute attrs[1];
    attrs[0].id = cudaLaunchAttributeProgrammaticStreamSerialization;
    attrs[0].val.programmaticStreamSerializationAllowed = 1;
    cfg.attrs = attrs;
    cfg.numAttrs = 1;

    cudaLaunchKernelEx(&cfg, torgb_kernel, (const float4*)x, bias, (float4*)out);
}